// round 1
// baseline (speedup 1.0000x reference)
#include <cuda_runtime.h>

#define Bb 8
#define Tt 2048
#define Vv 1024
#define BM 128
#define BN 128
#define BK 16
#define NTH 256

// ---- scratch (static __device__ — no allocations allowed) ----
__device__ float g_WkT[Vv * Vv];                 // 4 MB  WkT[a][o] = Wk[o][a]
__device__ float g_WqT[Vv * Vv];                 // 4 MB
__device__ float g_WvT[Vv * Vv];                 // 4 MB
__device__ float g_K[(size_t)Bb * Tt * Vv];      // 64 MB K[b][t][o]
__device__ float g_Ah[(size_t)Bb * Vv * Tt];     // 64 MB Ahat[b][a][s]

// ---------------------------------------------------------------------------
// Transpose the three weight matrices so gathers/GEMM loads are coalesced.
// ---------------------------------------------------------------------------
__global__ void transpose3(const float* __restrict__ Wk,
                           const float* __restrict__ Wq,
                           const float* __restrict__ Wv) {
    __shared__ float tile[32][33];
    const float* src;
    float* dst;
    if (blockIdx.z == 0)      { src = Wk; dst = g_WkT; }
    else if (blockIdx.z == 1) { src = Wq; dst = g_WqT; }
    else                      { src = Wv; dst = g_WvT; }
    int x = blockIdx.x * 32 + threadIdx.x;
    int y = blockIdx.y * 32 + threadIdx.y;
#pragma unroll
    for (int i = 0; i < 32; i += 8)
        tile[threadIdx.y + i][threadIdx.x] = src[(size_t)(y + i) * Vv + x];
    __syncthreads();
    x = blockIdx.y * 32 + threadIdx.x;
    y = blockIdx.x * 32 + threadIdx.y;
#pragma unroll
    for (int i = 0; i < 32; i += 8)
        dst[(size_t)(y + i) * Vv + x] = tile[threadIdx.x][threadIdx.y + i];
}

// ---------------------------------------------------------------------------
// Kernel 1: K[b][t][o] = sum_{s<=t} v[t-s] * WkT[idx[b][s]][o]
// A-operand is a lower-triangular Toeplitz generated from pv on the fly.
// k-tiles with s0 >= t0+BM are skipped entirely (causal).
// ---------------------------------------------------------------------------
__global__ __launch_bounds__(NTH)
void kernel_K(const float* __restrict__ pv, const int* __restrict__ idx) {
    const int b  = blockIdx.z;
    const int t0 = blockIdx.y * BM;
    const int n0 = blockIdx.x * BN;
    __shared__ __align__(16) float As[BK][BM];
    __shared__ __align__(16) float Bs[BK][BN];
    const int tid = threadIdx.x;
    const int tx = tid & 15;
    const int ty = tid >> 4;
    float acc[8][8];
#pragma unroll
    for (int i = 0; i < 8; i++)
#pragma unroll
        for (int j = 0; j < 8; j++) acc[i][j] = 0.f;

    const int fill_k  = tid >> 4;          // 0..15 (k row)
    const int fill_c0 = (tid & 15) * 8;    // 0..120 (col start)
    const int kend = t0 + BM;              // exclusive s bound
    for (int s0 = 0; s0 < kend; s0 += BK) {
        // A tile: Toeplitz from pv, masked below d=0 (this IS the tril)
        {
            const int d0 = (t0 + fill_c0) - (s0 + fill_k);
#pragma unroll
            for (int u = 0; u < 8; u++) {
                const int d = d0 + u;
                As[fill_k][fill_c0 + u] = (d >= 0) ? pv[d] : 0.f;
            }
        }
        // B tile: gathered WkT rows
        {
            const int is = idx[b * Tt + s0 + fill_k];
            const float* row = g_WkT + (size_t)is * Vv + n0 + fill_c0;
            const float4 v0 = *(const float4*)(row);
            const float4 v1 = *(const float4*)(row + 4);
            *(float4*)&Bs[fill_k][fill_c0]     = v0;
            *(float4*)&Bs[fill_k][fill_c0 + 4] = v1;
        }
        __syncthreads();
#pragma unroll
        for (int kk = 0; kk < BK; kk++) {
            float a[8], bv[8];
#pragma unroll
            for (int i = 0; i < 8; i++) a[i]  = As[kk][ty + 16 * i];
#pragma unroll
            for (int j = 0; j < 8; j++) bv[j] = Bs[kk][tx + 16 * j];
#pragma unroll
            for (int i = 0; i < 8; i++)
#pragma unroll
                for (int j = 0; j < 8; j++) acc[i][j] += a[i] * bv[j];
        }
        __syncthreads();
    }
#pragma unroll
    for (int i = 0; i < 8; i++) {
        float* orow = g_K + ((size_t)(b * Tt + t0 + ty + 16 * i)) * Vv + n0;
#pragma unroll
        for (int j = 0; j < 8; j++) orow[tx + 16 * j] = acc[i][j];
    }
}

// ---------------------------------------------------------------------------
// Kernel 2: Ahat[b][a][s] = sum_o WqT[a][o] * K[b][s][o]     (NT GEMM, V x T)
// Row-dedup of attention: only V=1024 distinct query rows instead of T=2048.
// ---------------------------------------------------------------------------
__global__ __launch_bounds__(NTH)
void kernel_Ah() {
    const int b  = blockIdx.z;
    const int a0 = blockIdx.y * BM;
    const int s0 = blockIdx.x * BN;
    __shared__ __align__(16) float As[BK][BM];
    __shared__ __align__(16) float Bs[BK][BN];
    const int tid = threadIdx.x;
    const int tx = tid & 15;
    const int ty = tid >> 4;
    float acc[8][8];
#pragma unroll
    for (int i = 0; i < 8; i++)
#pragma unroll
        for (int j = 0; j < 8; j++) acc[i][j] = 0.f;

    const int rm  = tid >> 1;          // 0..127 (tile row)
    const int kc0 = (tid & 1) * 8;     // 0 or 8 (k col start)
    for (int o0 = 0; o0 < Vv; o0 += BK) {
        {   // A tile (transpose load, K-contiguous rows of WqT)
            const float* row = g_WqT + (size_t)(a0 + rm) * Vv + o0 + kc0;
            const float4 v0 = *(const float4*)(row);
            const float4 v1 = *(const float4*)(row + 4);
            As[kc0 + 0][rm] = v0.x; As[kc0 + 1][rm] = v0.y;
            As[kc0 + 2][rm] = v0.z; As[kc0 + 3][rm] = v0.w;
            As[kc0 + 4][rm] = v1.x; As[kc0 + 5][rm] = v1.y;
            As[kc0 + 6][rm] = v1.z; As[kc0 + 7][rm] = v1.w;
        }
        {   // B tile (transpose load, K-contiguous rows of K[b])
            const float* row = g_K + ((size_t)(b * Tt + s0 + rm)) * Vv + o0 + kc0;
            const float4 v0 = *(const float4*)(row);
            const float4 v1 = *(const float4*)(row + 4);
            Bs[kc0 + 0][rm] = v0.x; Bs[kc0 + 1][rm] = v0.y;
            Bs[kc0 + 2][rm] = v0.z; Bs[kc0 + 3][rm] = v0.w;
            Bs[kc0 + 4][rm] = v1.x; Bs[kc0 + 5][rm] = v1.y;
            Bs[kc0 + 6][rm] = v1.z; Bs[kc0 + 7][rm] = v1.w;
        }
        __syncthreads();
#pragma unroll
        for (int kk = 0; kk < BK; kk++) {
            float a[8], bv[8];
#pragma unroll
            for (int i = 0; i < 8; i++) a[i]  = As[kk][ty + 16 * i];
#pragma unroll
            for (int j = 0; j < 8; j++) bv[j] = Bs[kk][tx + 16 * j];
#pragma unroll
            for (int i = 0; i < 8; i++)
#pragma unroll
                for (int j = 0; j < 8; j++) acc[i][j] += a[i] * bv[j];
        }
        __syncthreads();
    }
#pragma unroll
    for (int i = 0; i < 8; i++) {
        float* orow = g_Ah + ((size_t)(b * Vv + a0 + ty + 16 * i)) * Tt + s0;
#pragma unroll
        for (int j = 0; j < 8; j++) orow[tx + 16 * j] = acc[i][j];
    }
}

// ---------------------------------------------------------------------------
// Kernel 3: out[b][t][o] = 0.001 + sum_{s<=t} Ahat[b][idx[b][t]][s] * WvT[idx[b][s]][o]
// A rows gathered by idx[b][t]; B rows gathered by idx[b][s]; causal mask in
// A-tile fill; k-tiles above diagonal skipped.
// ---------------------------------------------------------------------------
__global__ __launch_bounds__(NTH)
void kernel_out(const int* __restrict__ idx, float* __restrict__ out) {
    const int b  = blockIdx.z;
    const int t0 = blockIdx.y * BM;
    const int n0 = blockIdx.x * BN;
    __shared__ __align__(16) float As[BK][BM];
    __shared__ __align__(16) float Bs[BK][BN];
    const int tid = threadIdx.x;
    const int tx = tid & 15;
    const int ty = tid >> 4;
    float acc[8][8];
#pragma unroll
    for (int i = 0; i < 8; i++)
#pragma unroll
        for (int j = 0; j < 8; j++) acc[i][j] = 0.f;

    const int rm  = tid >> 1;          // 0..127
    const int kc0 = (tid & 1) * 8;     // 0 or 8
    const int fill_k  = tid >> 4;      // 0..15
    const int fill_c0 = (tid & 15) * 8;

    const int tA = t0 + rm;                              // this thread's A row (t)
    const int ia = idx[b * Tt + tA];
    const float* arow = g_Ah + ((size_t)(b * Vv + ia)) * Tt;

    const int kend = t0 + BM;
    for (int s0 = 0; s0 < kend; s0 += BK) {
        {   // A tile: gathered Ahat row, causal-masked (s <= t)
            const float* row = arow + s0 + kc0;
            const float4 v0 = *(const float4*)(row);
            const float4 v1 = *(const float4*)(row + 4);
            const float vals[8] = {v0.x, v0.y, v0.z, v0.w, v1.x, v1.y, v1.z, v1.w};
#pragma unroll
            for (int u = 0; u < 8; u++)
                As[kc0 + u][rm] = (s0 + kc0 + u <= tA) ? vals[u] : 0.f;
        }
        {   // B tile: gathered WvT rows
            const int is = idx[b * Tt + s0 + fill_k];
            const float* row = g_WvT + (size_t)is * Vv + n0 + fill_c0;
            const float4 v0 = *(const float4*)(row);
            const float4 v1 = *(const float4*)(row + 4);
            *(float4*)&Bs[fill_k][fill_c0]     = v0;
            *(float4*)&Bs[fill_k][fill_c0 + 4] = v1;
        }
        __syncthreads();
#pragma unroll
        for (int kk = 0; kk < BK; kk++) {
            float a[8], bv[8];
#pragma unroll
            for (int i = 0; i < 8; i++) a[i]  = As[kk][ty + 16 * i];
#pragma unroll
            for (int j = 0; j < 8; j++) bv[j] = Bs[kk][tx + 16 * j];
#pragma unroll
            for (int i = 0; i < 8; i++)
#pragma unroll
                for (int j = 0; j < 8; j++) acc[i][j] += a[i] * bv[j];
        }
        __syncthreads();
    }
#pragma unroll
    for (int i = 0; i < 8; i++) {
        float* orow = out + ((size_t)(b * Tt + t0 + ty + 16 * i)) * Vv + n0;
#pragma unroll
        for (int j = 0; j < 8; j++) orow[tx + 16 * j] = acc[i][j] + 0.001f;
    }
}

// ---------------------------------------------------------------------------
extern "C" void kernel_launch(void* const* d_in, const int* in_sizes, int n_in,
                              void* d_out, int out_size) {
    const int*   idx = (const int*)d_in[0];
    const float* pv  = (const float*)d_in[1];
    const float* Wk  = (const float*)d_in[2];
    const float* Wq  = (const float*)d_in[3];
    const float* Wv  = (const float*)d_in[4];
    float* out = (float*)d_out;

    transpose3<<<dim3(Vv / 32, Vv / 32, 3), dim3(32, 8)>>>(Wk, Wq, Wv);
    kernel_K  <<<dim3(Vv / BN, Tt / BM, Bb), NTH>>>(pv, idx);
    kernel_Ah <<<dim3(Tt / BN, Vv / BM, Bb), NTH>>>();
    kernel_out<<<dim3(Vv / BN, Tt / BM, Bb), NTH>>>(idx, out);
}

// round 2
// speedup vs baseline: 2.7256x; 2.7256x over previous
#include <cuda_runtime.h>

#define Bb 8
#define Tt 2048
#define Vv 1024
#define BM 128
#define BN 128
#define BK 16
#define NTH 256

// ---- scratch (static __device__ — no allocations allowed) ----
__device__ float g_WkT[Vv * Vv];
__device__ float g_WqT[Vv * Vv];
__device__ float g_WvT[Vv * Vv];
__device__ float g_pv[Tt];
__device__ float g_K[(size_t)Bb * Tt * Vv];      // K[b][t][o]
__device__ float g_Ah[(size_t)Bb * Vv * Tt];     // Ahat[b][a][s]

__device__ __forceinline__ float tf32r(float x) {
    unsigned u;
    asm("cvt.rna.tf32.f32 %0, %1;" : "=r"(u) : "f"(x));
    return __uint_as_float(u);
}

__device__ __forceinline__ void mma_tf32(float& c0, float& c1, float& c2, float& c3,
                                         float a0, float a1, float a2, float a3,
                                         float b0, float b1) {
    asm volatile(
        "mma.sync.aligned.m16n8k8.row.col.f32.tf32.tf32.f32 "
        "{%0,%1,%2,%3}, {%4,%5,%6,%7}, {%8,%9}, {%0,%1,%2,%3};"
        : "+f"(c0), "+f"(c1), "+f"(c2), "+f"(c3)
        : "r"(__float_as_uint(a0)), "r"(__float_as_uint(a1)),
          "r"(__float_as_uint(a2)), "r"(__float_as_uint(a3)),
          "r"(__float_as_uint(b0)), "r"(__float_as_uint(b1)));
}

// swizzled column: makes all mma fragment LDS conflict-free
#define SW(c, k) (((c) + 8 * (k)) & 127)

// ---------------------------------------------------------------------------
__global__ void round_pv(const float* __restrict__ pv) {
    int i = blockIdx.x * 1024 + threadIdx.x;
    g_pv[i] = tf32r(pv[i]);
}

__global__ void transpose3(const float* __restrict__ Wk,
                           const float* __restrict__ Wq,
                           const float* __restrict__ Wv) {
    __shared__ float tile[32][33];
    const float* src;
    float* dst;
    if (blockIdx.z == 0)      { src = Wk; dst = g_WkT; }
    else if (blockIdx.z == 1) { src = Wq; dst = g_WqT; }
    else                      { src = Wv; dst = g_WvT; }
    int x = blockIdx.x * 32 + threadIdx.x;
    int y = blockIdx.y * 32 + threadIdx.y;
#pragma unroll
    for (int i = 0; i < 32; i += 8)
        tile[threadIdx.y + i][threadIdx.x] = src[(size_t)(y + i) * Vv + x];
    __syncthreads();
    x = blockIdx.y * 32 + threadIdx.x;
    y = blockIdx.x * 32 + threadIdx.y;
#pragma unroll
    for (int i = 0; i < 32; i += 8)
        dst[(size_t)(y + i) * Vv + x] = tf32r(tile[threadIdx.x][threadIdx.y + i]);
}

// ---------------------------------------------------------------------------
// Shared warp-MMA core: consumes As/Bs (swizzled), accumulates acc[2][8][4].
// Warp tile 32(m) x 64(n); 8 warps: 4 in m, 2 in n.
// ---------------------------------------------------------------------------
struct Frag { float acc[2][8][4]; };

__device__ __forceinline__ void mma_chunk(const float (*As)[BM], const float (*Bs)[BN],
                                          int wm, int wn, int gid, int kq, Frag& f) {
#pragma unroll
    for (int kk0 = 0; kk0 < BK; kk0 += 8) {
        float a[2][4];
#pragma unroll
        for (int mf = 0; mf < 2; mf++) {
            const int k1 = kk0 + kq, k2 = kk0 + kq + 4;
            const int m1 = wm + mf * 16 + gid, m2 = m1 + 8;
            a[mf][0] = As[k1][SW(m1, k1)];
            a[mf][1] = As[k1][SW(m2, k1)];
            a[mf][2] = As[k2][SW(m1, k2)];
            a[mf][3] = As[k2][SW(m2, k2)];
        }
#pragma unroll
        for (int nf = 0; nf < 8; nf++) {
            const int k1 = kk0 + kq, k2 = kk0 + kq + 4;
            const int n = wn + nf * 8 + gid;
            float b0 = Bs[k1][SW(n, k1)];
            float b1 = Bs[k2][SW(n, k2)];
#pragma unroll
            for (int mf = 0; mf < 2; mf++)
                mma_tf32(f.acc[mf][nf][0], f.acc[mf][nf][1], f.acc[mf][nf][2], f.acc[mf][nf][3],
                         a[mf][0], a[mf][1], a[mf][2], a[mf][3], b0, b1);
        }
    }
}

// ---------------------------------------------------------------------------
// Kernel 1: K[b][t][o] = sum_{s<=t} pv[t-s] * WkT[idx[b][s]][o]
// ---------------------------------------------------------------------------
__global__ __launch_bounds__(NTH)
void kernel_K(const int* __restrict__ idx) {
    const int b  = blockIdx.z;
    const int t0 = blockIdx.y * BM;
    const int n0 = blockIdx.x * BN;
    __shared__ __align__(16) float As[BK][BM];
    __shared__ __align__(16) float Bs[BK][BN];
    const int tid = threadIdx.x;
    const int wid = tid >> 5, lane = tid & 31;
    const int wm = (wid & 3) * 32, wn = (wid >> 2) * 64;
    const int gid = lane >> 2, kq = lane & 3;
    Frag f;
#pragma unroll
    for (int mf = 0; mf < 2; mf++)
#pragma unroll
        for (int nf = 0; nf < 8; nf++)
#pragma unroll
            for (int c = 0; c < 4; c++) f.acc[mf][nf][c] = 0.f;

    const int fill_k  = tid >> 4;
    const int fill_c0 = (tid & 15) * 8;
    const int kend = t0 + BM;
    for (int s0 = 0; s0 < kend; s0 += BK) {
        {   // A: Toeplitz from g_pv (pre-rounded), tril mask = d>=0
            const int d0 = (t0 + fill_c0) - (s0 + fill_k);
            float vals[8];
#pragma unroll
            for (int u = 0; u < 8; u++) {
                const int d = d0 + u;
                vals[u] = (d >= 0) ? g_pv[d] : 0.f;
            }
            float* dst = &As[fill_k][SW(fill_c0, fill_k)];
            *(float4*)dst       = make_float4(vals[0], vals[1], vals[2], vals[3]);
            *(float4*)(dst + 4) = make_float4(vals[4], vals[5], vals[6], vals[7]);
        }
        {   // B: gathered WkT rows (pre-rounded)
            const int is = idx[b * Tt + s0 + fill_k];
            const float* row = g_WkT + (size_t)is * Vv + n0 + fill_c0;
            const float4 v0 = *(const float4*)(row);
            const float4 v1 = *(const float4*)(row + 4);
            float* dst = &Bs[fill_k][SW(fill_c0, fill_k)];
            *(float4*)dst       = v0;
            *(float4*)(dst + 4) = v1;
        }
        __syncthreads();
        mma_chunk(As, Bs, wm, wn, gid, kq, f);
        __syncthreads();
    }
#pragma unroll
    for (int mf = 0; mf < 2; mf++)
#pragma unroll
        for (int h = 0; h < 2; h++) {
            const int row = t0 + wm + mf * 16 + gid + 8 * h;
            float* orow = g_K + ((size_t)(b * Tt + row)) * Vv + n0 + wn;
#pragma unroll
            for (int nf = 0; nf < 8; nf++)
                *(float2*)&orow[nf * 8 + kq * 2] =
                    make_float2(f.acc[mf][nf][2 * h], f.acc[mf][nf][2 * h + 1]);
        }
}

// ---------------------------------------------------------------------------
// Kernel 2: Ahat[b][a][s] = sum_o WqT[a][o] * K[b][s][o]   (NT, V x T)
// ---------------------------------------------------------------------------
__global__ __launch_bounds__(NTH)
void kernel_Ah() {
    const int b  = blockIdx.z;
    const int a0 = blockIdx.y * BM;
    const int s0 = blockIdx.x * BN;
    __shared__ __align__(16) float As[BK][BM];
    __shared__ __align__(16) float Bs[BK][BN];
    const int tid = threadIdx.x;
    const int wid = tid >> 5, lane = tid & 31;
    const int wm = (wid & 3) * 32, wn = (wid >> 2) * 64;
    const int gid = lane >> 2, kq = lane & 3;
    Frag f;
#pragma unroll
    for (int mf = 0; mf < 2; mf++)
#pragma unroll
        for (int nf = 0; nf < 8; nf++)
#pragma unroll
            for (int c = 0; c < 4; c++) f.acc[mf][nf][c] = 0.f;

    const int rm  = tid >> 1;
    const int kc0 = (tid & 1) * 8;
    for (int o0 = 0; o0 < Vv; o0 += BK) {
        {   // A: WqT rows, transpose into As (pre-rounded)
            const float* row = g_WqT + (size_t)(a0 + rm) * Vv + o0 + kc0;
            const float4 v0 = *(const float4*)(row);
            const float4 v1 = *(const float4*)(row + 4);
            const float vals[8] = {v0.x, v0.y, v0.z, v0.w, v1.x, v1.y, v1.z, v1.w};
#pragma unroll
            for (int u = 0; u < 8; u++) {
                const int k = kc0 + u;
                As[k][SW(rm, k)] = vals[u];
            }
        }
        {   // B: K rows, transpose into Bs (round to tf32 here)
            const float* row = g_K + ((size_t)(b * Tt + s0 + rm)) * Vv + o0 + kc0;
            const float4 v0 = *(const float4*)(row);
            const float4 v1 = *(const float4*)(row + 4);
            const float vals[8] = {v0.x, v0.y, v0.z, v0.w, v1.x, v1.y, v1.z, v1.w};
#pragma unroll
            for (int u = 0; u < 8; u++) {
                const int k = kc0 + u;
                Bs[k][SW(rm, k)] = tf32r(vals[u]);
            }
        }
        __syncthreads();
        mma_chunk(As, Bs, wm, wn, gid, kq, f);
        __syncthreads();
    }
#pragma unroll
    for (int mf = 0; mf < 2; mf++)
#pragma unroll
        for (int h = 0; h < 2; h++) {
            const int row = a0 + wm + mf * 16 + gid + 8 * h;
            float* orow = g_Ah + ((size_t)(b * Vv + row)) * Tt + s0 + wn;
#pragma unroll
            for (int nf = 0; nf < 8; nf++)
                *(float2*)&orow[nf * 8 + kq * 2] =
                    make_float2(f.acc[mf][nf][2 * h], f.acc[mf][nf][2 * h + 1]);
        }
}

// ---------------------------------------------------------------------------
// Kernel 3: out[b][t][o] = 1e-3 + sum_{s<=t} Ahat[b][idx[b][t]][s]*WvT[idx[b][s]][o]
// ---------------------------------------------------------------------------
__global__ __launch_bounds__(NTH)
void kernel_out(const int* __restrict__ idx, float* __restrict__ out) {
    const int b  = blockIdx.z;
    const int t0 = blockIdx.y * BM;
    const int n0 = blockIdx.x * BN;
    __shared__ __align__(16) float As[BK][BM];
    __shared__ __align__(16) float Bs[BK][BN];
    const int tid = threadIdx.x;
    const int wid = tid >> 5, lane = tid & 31;
    const int wm = (wid & 3) * 32, wn = (wid >> 2) * 64;
    const int gid = lane >> 2, kq = lane & 3;
    Frag f;
#pragma unroll
    for (int mf = 0; mf < 2; mf++)
#pragma unroll
        for (int nf = 0; nf < 8; nf++)
#pragma unroll
            for (int c = 0; c < 4; c++) f.acc[mf][nf][c] = 0.f;

    const int rm  = tid >> 1;
    const int kc0 = (tid & 1) * 8;
    const int fill_k  = tid >> 4;
    const int fill_c0 = (tid & 15) * 8;

    const int tA = t0 + rm;
    const int ia = idx[b * Tt + tA];
    const float* arow = g_Ah + ((size_t)(b * Vv + ia)) * Tt;

    const int kend = t0 + BM;
    for (int s0 = 0; s0 < kend; s0 += BK) {
        {   // A: gathered Ahat row, causal mask s<=t, round to tf32
            const float* row = arow + s0 + kc0;
            const float4 v0 = *(const float4*)(row);
            const float4 v1 = *(const float4*)(row + 4);
            const float vals[8] = {v0.x, v0.y, v0.z, v0.w, v1.x, v1.y, v1.z, v1.w};
#pragma unroll
            for (int u = 0; u < 8; u++) {
                const int k = kc0 + u;
                As[k][SW(rm, k)] = (s0 + k <= tA) ? tf32r(vals[u]) : 0.f;
            }
        }
        {   // B: gathered WvT rows (pre-rounded)
            const int is = idx[b * Tt + s0 + fill_k];
            const float* row = g_WvT + (size_t)is * Vv + n0 + fill_c0;
            const float4 v0 = *(const float4*)(row);
            const float4 v1 = *(const float4*)(row + 4);
            float* dst = &Bs[fill_k][SW(fill_c0, fill_k)];
            *(float4*)dst       = v0;
            *(float4*)(dst + 4) = v1;
        }
        __syncthreads();
        mma_chunk(As, Bs, wm, wn, gid, kq, f);
        __syncthreads();
    }
#pragma unroll
    for (int mf = 0; mf < 2; mf++)
#pragma unroll
        for (int h = 0; h < 2; h++) {
            const int row = t0 + wm + mf * 16 + gid + 8 * h;
            float* orow = out + ((size_t)(b * Tt + row)) * Vv + n0 + wn;
#pragma unroll
            for (int nf = 0; nf < 8; nf++)
                *(float2*)&orow[nf * 8 + kq * 2] =
                    make_float2(f.acc[mf][nf][2 * h] + 0.001f,
                                f.acc[mf][nf][2 * h + 1] + 0.001f);
        }
}

// ---------------------------------------------------------------------------
extern "C" void kernel_launch(void* const* d_in, const int* in_sizes, int n_in,
                              void* d_out, int out_size) {
    const int*   idx = (const int*)d_in[0];
    const float* pv  = (const float*)d_in[1];
    const float* Wk  = (const float*)d_in[2];
    const float* Wq  = (const float*)d_in[3];
    const float* Wv  = (const float*)d_in[4];
    float* out = (float*)d_out;

    round_pv  <<<Tt / 1024, 1024>>>(pv);
    transpose3<<<dim3(Vv / 32, Vv / 32, 3), dim3(32, 8)>>>(Wk, Wq, Wv);
    kernel_K  <<<dim3(Vv / BN, Tt / BM, Bb), NTH>>>(idx);
    kernel_Ah <<<dim3(Tt / BN, Vv / BM, Bb), NTH>>>();
    kernel_out<<<dim3(Vv / BN, Tt / BM, Bb), NTH>>>(idx, out);
}

// round 5
// speedup vs baseline: 2.8591x; 1.0490x over previous
#include <cuda_runtime.h>
#include <cstdint>

#define Bb 8
#define Tt 2048
#define Vv 1024
#define BM 128
#define BN 128
#define BK 32
#define NTH 128

// ---- scratch (static __device__ — no allocations allowed) ----
__device__ float g_WkT[Vv * Vv];
__device__ float g_WqT[Vv * Vv];
__device__ float g_WvT[Vv * Vv];
__device__ float g_pv[Tt];
__device__ float g_K [(size_t)Bb * Tt * Vv];   // K[b][t][o]   (tf32-rounded)
__device__ float g_Ah[(size_t)Bb * Vv * Tt];   // Ahat[b][a][s] (tf32-rounded)
__device__ float g_Gk[(size_t)Bb * Vv * Tt];   // Gk[b][o][s] = WkT[idx[b][s]][o]
__device__ float g_Gv[(size_t)Bb * Vv * Tt];   // Gv[b][o][s] = WvT[idx[b][s]][o]

// ---------------- helpers ----------------
__device__ __forceinline__ uint32_t smem_u32(const void* p) {
    uint32_t a;
    asm("{ .reg .u64 t; cvta.to.shared.u64 t, %1; cvt.u32.u64 %0, t; }" : "=r"(a) : "l"(p));
    return a;
}
__device__ __forceinline__ float tf32r(float x) {
    unsigned u;
    asm("cvt.rna.tf32.f32 %0, %1;" : "=r"(u) : "f"(x));
    return __uint_as_float(u);
}
__device__ __forceinline__ void cpa16(uint32_t dst, const void* src) {
    asm volatile("cp.async.cg.shared.global [%0], [%1], 16;" :: "r"(dst), "l"(src) : "memory");
}
#define CP_COMMIT() asm volatile("cp.async.commit_group;" ::: "memory")
#define CP_WAIT1()  asm volatile("cp.async.wait_group 1;" ::: "memory")
#define CP_WAIT0()  asm volatile("cp.async.wait_group 0;" ::: "memory")

__device__ __forceinline__ void mma_tf32(float* c, const float* a, float b0, float b1) {
    asm volatile(
        "mma.sync.aligned.m16n8k8.row.col.f32.tf32.tf32.f32 "
        "{%0,%1,%2,%3}, {%4,%5,%6,%7}, {%8,%9}, {%0,%1,%2,%3};"
        : "+f"(c[0]), "+f"(c[1]), "+f"(c[2]), "+f"(c[3])
        : "r"(__float_as_uint(a[0])), "r"(__float_as_uint(a[1])),
          "r"(__float_as_uint(a[2])), "r"(__float_as_uint(a[3])),
          "r"(__float_as_uint(b0)), "r"(__float_as_uint(b1)));
}

// byte-offset swizzle for [row][k] tiles with 128B rows (conflict-free frags)
__device__ __forceinline__ uint32_t swz(uint32_t off) { return off ^ ((off >> 3) & 0x70); }

// ---------------- prep kernels ----------------
__global__ void round_pv(const float* __restrict__ pv) {
    int i = blockIdx.x * 1024 + threadIdx.x;
    g_pv[i] = tf32r(pv[i]);
}

__global__ void transpose3(const float* __restrict__ Wk,
                           const float* __restrict__ Wq,
                           const float* __restrict__ Wv) {
    __shared__ float tile[32][33];
    const float* src;
    float* dst;
    if (blockIdx.z == 0)      { src = Wk; dst = g_WkT; }
    else if (blockIdx.z == 1) { src = Wq; dst = g_WqT; }
    else                      { src = Wv; dst = g_WvT; }
    int x = blockIdx.x * 32 + threadIdx.x;
    int y = blockIdx.y * 32 + threadIdx.y;
#pragma unroll
    for (int i = 0; i < 32; i += 8)
        tile[threadIdx.y + i][threadIdx.x] = src[(size_t)(y + i) * Vv + x];
    __syncthreads();
    x = blockIdx.y * 32 + threadIdx.x;
    y = blockIdx.x * 32 + threadIdx.y;
#pragma unroll
    for (int i = 0; i < 32; i += 8)
        dst[(size_t)(y + i) * Vv + x] = tf32r(tile[threadIdx.x][threadIdx.y + i]);
}

// Gk[b][o][s] = WkT[idx[b][s]][o]; Gv likewise (z = b*2 + which)
__global__ void gatherT(const int* __restrict__ idx) {
    __shared__ float tile[32][33];
    const int z = blockIdx.z;
    const int b = z >> 1;
    const float* WT = (z & 1) ? g_WvT : g_WkT;
    float* G        = (z & 1) ? g_Gv  : g_Gk;
    const int o0 = blockIdx.x * 32, s0 = blockIdx.y * 32;
    const int tx = threadIdx.x, ty = threadIdx.y;
#pragma unroll
    for (int i = 0; i < 32; i += 8) {
        const int row = idx[b * Tt + s0 + ty + i];
        tile[ty + i][tx] = WT[(size_t)row * Vv + o0 + tx];
    }
    __syncthreads();
#pragma unroll
    for (int i = 0; i < 32; i += 8)
        G[((size_t)(b * Vv + o0 + ty + i)) * Tt + s0 + tx] = tile[tx][ty + i];
}

// ---------------- MMA core: one BK=32 chunk, warp tile 64x64 ----------------
__device__ __forceinline__ void mma_chunk32(const char* A, const char* B,
                                            int wm, int wn, int gid, int kq,
                                            float acc[4][8][4]) {
#pragma unroll
    for (int k8 = 0; k8 < 4; k8++) {
        const int k1 = k8 * 8 + kq, k2 = k1 + 4;
        float a[4][4];
#pragma unroll
        for (int mf = 0; mf < 4; mf++) {
            const int m1 = wm + mf * 16 + gid;
            a[mf][0] = *(const float*)(A + swz(m1 * 128 + k1 * 4));
            a[mf][1] = *(const float*)(A + swz((m1 + 8) * 128 + k1 * 4));
            a[mf][2] = *(const float*)(A + swz(m1 * 128 + k2 * 4));
            a[mf][3] = *(const float*)(A + swz((m1 + 8) * 128 + k2 * 4));
        }
#pragma unroll
        for (int nf = 0; nf < 8; nf++) {
            const int n = wn + nf * 8 + gid;
            const float b0 = *(const float*)(B + swz(n * 128 + k1 * 4));
            const float b1 = *(const float*)(B + swz(n * 128 + k2 * 4));
#pragma unroll
            for (int mf = 0; mf < 4; mf++)
                mma_tf32(acc[mf][nf], a[mf], b0, b1);
        }
    }
}

#define GEMM_VARS() \
    extern __shared__ char dsm[]; \
    const int tid = threadIdx.x; \
    const int wid = tid >> 5, lane = tid & 31; \
    const int gid = lane >> 2, kq = lane & 3; \
    const int wm = (wid & 1) * 64, wn = (wid >> 1) * 64; \
    float acc[4][8][4]; \
    _Pragma("unroll") for (int mf = 0; mf < 4; mf++) \
    _Pragma("unroll") for (int nf = 0; nf < 8; nf++) \
    _Pragma("unroll") for (int c = 0; c < 4; c++) acc[mf][nf][c] = 0.f;

// ---------------------------------------------------------------------------
// Kernel 1: g_K[b][t][o] = tf32( sum_{s<=t} pv[t-s] * Gk[b][o][s] )
// ---------------------------------------------------------------------------
__global__ __launch_bounds__(NTH)
void kernel_K() {
    const int b  = blockIdx.z;
    const int t0 = blockIdx.y * BM;
    const int n0 = blockIdx.x * BN;
    GEMM_VARS();
    const int nt = t0 / BK + 4;
    const int t = t0 + tid;
    const float* bsrc0 = g_Gk + ((size_t)(b * Vv + n0 + tid)) * Tt;

    // fill: A manual Toeplitz (masked), B cp.async
    auto fill = [&](int kt, int p) {
        char* Ab = dsm + p * 32768;
        const uint32_t bu = smem_u32(Ab + 16384);
        const int s0 = kt * BK;
        const uint32_t arow = tid * 128;
#pragma unroll
        for (int ch = 0; ch < 8; ch++) {
            const int s = s0 + ch * 4;
            float4 v;
            v.x = (t - s     >= 0) ? g_pv[t - s]     : 0.f;
            v.y = (t - s - 1 >= 0) ? g_pv[t - s - 1] : 0.f;
            v.z = (t - s - 2 >= 0) ? g_pv[t - s - 2] : 0.f;
            v.w = (t - s - 3 >= 0) ? g_pv[t - s - 3] : 0.f;
            *(float4*)(Ab + swz(arow + ch * 16)) = v;
            cpa16(bu + swz(arow + ch * 16), bsrc0 + s);
        }
    };

    fill(0, 0); CP_COMMIT();
    fill(1, 1); CP_COMMIT();
    for (int kt = 0; kt < nt; kt++) {
        const int p = kt & 1;
        if (kt + 1 < nt) CP_WAIT1(); else CP_WAIT0();
        __syncthreads();
        mma_chunk32(dsm + p * 32768, dsm + p * 32768 + 16384, wm, wn, gid, kq, acc);
        if (kt + 2 < nt) {
            __syncthreads();
            fill(kt + 2, p); CP_COMMIT();
        }
    }
#pragma unroll
    for (int mf = 0; mf < 4; mf++)
#pragma unroll
        for (int h = 0; h < 2; h++) {
            const int row = t0 + wm + mf * 16 + gid + 8 * h;
            float* orow = g_K + ((size_t)(b * Tt + row)) * Vv + n0 + wn;
#pragma unroll
            for (int nf = 0; nf < 8; nf++)
                *(float2*)&orow[nf * 8 + kq * 2] =
                    make_float2(tf32r(acc[mf][nf][2 * h]), tf32r(acc[mf][nf][2 * h + 1]));
        }
}

// ---------------------------------------------------------------------------
// Kernel 2: g_Ah[b][a][s] = tf32( sum_o WqT[a][o] * g_K[b][s][o] )
// ---------------------------------------------------------------------------
__global__ __launch_bounds__(NTH)
void kernel_Ah() {
    const int b  = blockIdx.z;
    const int a0 = blockIdx.y * BM;
    const int sb = blockIdx.x * BN;
    GEMM_VARS();
    const int nt = Vv / BK;   // 32
    const float* asrc0 = g_WqT + (size_t)(a0 + tid) * Vv;
    const float* bsrc0 = g_K + ((size_t)(b * Tt + sb + tid)) * Vv;

    auto fill = [&](int kt, int p) {
        char* Ab = dsm + p * 32768;
        const uint32_t au = smem_u32(Ab);
        const uint32_t bu = au + 16384;
        const int o0 = kt * BK;
        const uint32_t arow = tid * 128;
#pragma unroll
        for (int ch = 0; ch < 8; ch++) {
            cpa16(au + swz(arow + ch * 16), asrc0 + o0 + ch * 4);
            cpa16(bu + swz(arow + ch * 16), bsrc0 + o0 + ch * 4);
        }
    };

    fill(0, 0); CP_COMMIT();
    fill(1, 1); CP_COMMIT();
    for (int kt = 0; kt < nt; kt++) {
        const int p = kt & 1;
        if (kt + 1 < nt) CP_WAIT1(); else CP_WAIT0();
        __syncthreads();
        mma_chunk32(dsm + p * 32768, dsm + p * 32768 + 16384, wm, wn, gid, kq, acc);
        if (kt + 2 < nt) {
            __syncthreads();
            fill(kt + 2, p); CP_COMMIT();
        }
    }
#pragma unroll
    for (int mf = 0; mf < 4; mf++)
#pragma unroll
        for (int h = 0; h < 2; h++) {
            const int row = a0 + wm + mf * 16 + gid + 8 * h;
            float* orow = g_Ah + ((size_t)(b * Vv + row)) * Tt + sb + wn;
#pragma unroll
            for (int nf = 0; nf < 8; nf++)
                *(float2*)&orow[nf * 8 + kq * 2] =
                    make_float2(tf32r(acc[mf][nf][2 * h]), tf32r(acc[mf][nf][2 * h + 1]));
        }
}

// ---------------------------------------------------------------------------
// Kernel 3: out[b][t][o] = 1e-3 + sum_{s<=t} Ah[b][idx[b][t]][s] * Gv[b][o][s]
// ---------------------------------------------------------------------------
__global__ __launch_bounds__(NTH)
void kernel_out(const int* __restrict__ idx, float* __restrict__ out) {
    const int b  = blockIdx.z;
    const int t0 = blockIdx.y * BM;
    const int n0 = blockIdx.x * BN;
    GEMM_VARS();
    const int nt = t0 / BK + 4;
    const int t = t0 + tid;
    const int ia = idx[b * Tt + t];
    const float* asrc0 = g_Ah + ((size_t)(b * Vv + ia)) * Tt;
    const float* bsrc0 = g_Gv + ((size_t)(b * Vv + n0 + tid)) * Tt;

    auto fill = [&](int kt, int p) {
        char* Ab = dsm + p * 32768;
        const uint32_t au = smem_u32(Ab);
        const uint32_t bu = au + 16384;
        const int s0 = kt * BK;
        const uint32_t arow = tid * 128;
        if (kt >= nt - 4) {
            // diagonal region: manual masked A fill
#pragma unroll
            for (int ch = 0; ch < 8; ch++) {
                const int s = s0 + ch * 4;
                float4 v = *(const float4*)(asrc0 + s);
                v.x = (s     <= t) ? v.x : 0.f;
                v.y = (s + 1 <= t) ? v.y : 0.f;
                v.z = (s + 2 <= t) ? v.z : 0.f;
                v.w = (s + 3 <= t) ? v.w : 0.f;
                *(float4*)(Ab + swz(arow + ch * 16)) = v;
                cpa16(bu + swz(arow + ch * 16), bsrc0 + s);
            }
        } else {
#pragma unroll
            for (int ch = 0; ch < 8; ch++) {
                cpa16(au + swz(arow + ch * 16), asrc0 + s0 + ch * 4);
                cpa16(bu + swz(arow + ch * 16), bsrc0 + s0 + ch * 4);
            }
        }
    };

    fill(0, 0); CP_COMMIT();
    fill(1, 1); CP_COMMIT();
    for (int kt = 0; kt < nt; kt++) {
        const int p = kt & 1;
        if (kt + 1 < nt) CP_WAIT1(); else CP_WAIT0();
        __syncthreads();
        mma_chunk32(dsm + p * 32768, dsm + p * 32768 + 16384, wm, wn, gid, kq, acc);
        if (kt + 2 < nt) {
            __syncthreads();
            fill(kt + 2, p); CP_COMMIT();
        }
    }
#pragma unroll
    for (int mf = 0; mf < 4; mf++)
#pragma unroll
        for (int h = 0; h < 2; h++) {
            const int row = t0 + wm + mf * 16 + gid + 8 * h;
            float* orow = out + ((size_t)(b * Tt + row)) * Vv + n0 + wn;
#pragma unroll
            for (int nf = 0; nf < 8; nf++)
                *(float2*)&orow[nf * 8 + kq * 2] =
                    make_float2(acc[mf][nf][2 * h] + 0.001f, acc[mf][nf][2 * h + 1] + 0.001f);
        }
}

// ---------------------------------------------------------------------------
extern "C" void kernel_launch(void* const* d_in, const int* in_sizes, int n_in,
                              void* d_out, int out_size) {
    const int*   idx = (const int*)d_in[0];
    const float* pv  = (const float*)d_in[1];
    const float* Wk  = (const float*)d_in[2];
    const float* Wq  = (const float*)d_in[3];
    const float* Wv  = (const float*)d_in[4];
    float* out = (float*)d_out;

    const int dynsmem = 65536;
    cudaFuncSetAttribute(kernel_K,   cudaFuncAttributeMaxDynamicSharedMemorySize, dynsmem);
    cudaFuncSetAttribute(kernel_Ah,  cudaFuncAttributeMaxDynamicSharedMemorySize, dynsmem);
    cudaFuncSetAttribute(kernel_out, cudaFuncAttributeMaxDynamicSharedMemorySize, dynsmem);

    round_pv  <<<Tt / 1024, 1024>>>(pv);
    transpose3<<<dim3(Vv / 32, Vv / 32, 3), dim3(32, 8)>>>(Wk, Wq, Wv);
    gatherT   <<<dim3(Vv / 32, Tt / 32, Bb * 2), dim3(32, 8)>>>(idx);
    kernel_K  <<<dim3(Vv / BN, Tt / BM, Bb), NTH, dynsmem>>>();
    kernel_Ah <<<dim3(Tt / BN, Vv / BM, Bb), NTH, dynsmem>>>();
    kernel_out<<<dim3(Vv / BN, Tt / BM, Bb), NTH, dynsmem>>>(idx, out);
}

// round 7
// speedup vs baseline: 3.9069x; 1.3664x over previous
#include <cuda_runtime.h>
#include <cstdint>

#define Bb 8
#define Tt 2048
#define Vv 1024
#define BM 128
#define BN 128
#define BK 32
#define NTH 128
#define BUFB 32768

// ---- scratch (static __device__ — no allocations allowed) ----
__device__ float g_WkT[Vv * Vv];
__device__ float g_WqT[Vv * Vv];
__device__ float g_WvT[Vv * Vv];
__device__ float g_pv[Tt];
__device__ float g_CT[Vv * Vv];                 // CT[i][a] = (Wq^T Wk)[a][i]
__device__ float g_Cg[(size_t)Bb * Vv * Tt];    // Cg[b][a][s'] = CT[idx[b][s']][a]
__device__ float g_Gv[(size_t)Bb * Vv * Tt];    // Gv[b][o][s]  = WvT[idx[b][s]][o]
__device__ float g_Ah[(size_t)Bb * Vv * Tt];    // Ah[b][a][s]

// ---------------- helpers ----------------
__device__ __forceinline__ uint32_t smem_u32(const void* p) {
    uint32_t a;
    asm("{ .reg .u64 t; cvta.to.shared.u64 t, %1; cvt.u32.u64 %0, t; }" : "=r"(a) : "l"(p));
    return a;
}
__device__ __forceinline__ float tf32r(float x) {
    unsigned u;
    asm("cvt.rna.tf32.f32 %0, %1;" : "=r"(u) : "f"(x));
    return __uint_as_float(u);
}
__device__ __forceinline__ void cpa16(uint32_t dst, const void* src) {
    asm volatile("cp.async.cg.shared.global [%0], [%1], 16;" :: "r"(dst), "l"(src) : "memory");
}
#define CP_COMMIT() asm volatile("cp.async.commit_group;" ::: "memory")
#define CP_WAIT1()  asm volatile("cp.async.wait_group 1;" ::: "memory")
#define CP_WAIT0()  asm volatile("cp.async.wait_group 0;" ::: "memory")

__device__ __forceinline__ void mma_tf32(float* c, const float* a, float b0, float b1) {
    asm volatile(
        "mma.sync.aligned.m16n8k8.row.col.f32.tf32.tf32.f32 "
        "{%0,%1,%2,%3}, {%4,%5,%6,%7}, {%8,%9}, {%0,%1,%2,%3};"
        : "+f"(c[0]), "+f"(c[1]), "+f"(c[2]), "+f"(c[3])
        : "r"(__float_as_uint(a[0])), "r"(__float_as_uint(a[1])),
          "r"(__float_as_uint(a[2])), "r"(__float_as_uint(a[3])),
          "r"(__float_as_uint(b0)), "r"(__float_as_uint(b1)));
}

// ---------------- MMA core: one BK=32 chunk, warp tile 64x64 ----------------
// Tile layout [row][k], 128B rows, swizzle folded into ko[] (bank-conflict-free).
__device__ __forceinline__ void mma_chunk(const char* Atp, const char* Btp,
                                          const uint32_t* ko, float acc[4][8][4]) {
#pragma unroll
    for (int k8 = 0; k8 < 4; k8++) {
        const char* a0p = Atp + ko[k8 * 2 + 0];
        const char* a1p = Atp + ko[k8 * 2 + 1];
        const char* b0p = Btp + ko[k8 * 2 + 0];
        const char* b1p = Btp + ko[k8 * 2 + 1];
        float a[4][4];
#pragma unroll
        for (int mf = 0; mf < 4; mf++) {
            a[mf][0] = *(const float*)(a0p + mf * 2048);
            a[mf][1] = *(const float*)(a0p + mf * 2048 + 1024);
            a[mf][2] = *(const float*)(a1p + mf * 2048);
            a[mf][3] = *(const float*)(a1p + mf * 2048 + 1024);
        }
#pragma unroll
        for (int nf = 0; nf < 8; nf++) {
            const float b0 = *(const float*)(b0p + nf * 1024);
            const float b1 = *(const float*)(b1p + nf * 1024);
#pragma unroll
            for (int mf = 0; mf < 4; mf++)
                mma_tf32(acc[mf][nf], a[mf], b0, b1);
        }
    }
}

#define GEMM_PROLOG() \
    extern __shared__ char dsm[]; \
    const int tid = threadIdx.x; \
    const int wid = tid >> 5, lane = tid & 31; \
    const int gid = lane >> 2, kq = lane & 3; \
    const int wm = (wid & 1) * 64, wn = (wid >> 1) * 64; \
    uint32_t ko[8]; \
    { const uint32_t xg = (uint32_t)(gid & 7) << 4; \
      _Pragma("unroll") for (int k8 = 0; k8 < 4; k8++) \
      _Pragma("unroll") for (int h = 0; h < 2; h++) \
          ko[k8 * 2 + h] = ((uint32_t)((k8 * 8 + kq + h * 4) * 4)) ^ xg; } \
    const char* Abase = dsm + (wm + gid) * 128; \
    const char* Bbase = dsm + 16384 + (wn + gid) * 128; \
    char* fAp = dsm + tid * 128; \
    char* fBp = fAp + 16384; \
    const uint32_t fA = smem_u32(fAp); \
    const uint32_t fB = fA + 16384; \
    const uint32_t fxg = (uint32_t)(tid & 7) << 4; \
    (void)fBp; (void)fB; \
    float acc[4][8][4]; \
    _Pragma("unroll") for (int mf = 0; mf < 4; mf++) \
    _Pragma("unroll") for (int nf = 0; nf < 8; nf++) \
    _Pragma("unroll") for (int c = 0; c < 4; c++) acc[mf][nf][c] = 0.f;

// triple-buffered mainloop: fill 2 ahead, one sync per chunk
#define GEMM_LOOP(nt, FILL) \
    FILL(0, 0u); CP_COMMIT(); \
    FILL(1, (uint32_t)BUFB); CP_COMMIT(); \
    { int p = 0; \
      for (int kt = 0; kt < (nt); kt++) { \
          if (kt + 1 < (nt)) CP_WAIT1(); else CP_WAIT0(); \
          __syncthreads(); \
          if (kt + 2 < (nt)) { \
              const int p2 = (p >= 1) ? p - 1 : 2; \
              FILL(kt + 2, (uint32_t)(p2 * BUFB)); CP_COMMIT(); \
          } \
          mma_chunk(Abase + p * BUFB, Bbase + p * BUFB, ko, acc); \
          p = (p == 2) ? 0 : p + 1; \
      } }

#define GEMM_EPI(dstptr, ldT, ROWBASE, COLBASE, XF) \
    _Pragma("unroll") for (int mf = 0; mf < 4; mf++) \
    _Pragma("unroll") for (int h = 0; h < 2; h++) { \
        const int row_ = (ROWBASE) + wm + mf * 16 + gid + 8 * h; \
        float* orow_ = (dstptr) + (size_t)row_ * (ldT) + (COLBASE) + wn; \
        _Pragma("unroll") for (int nf = 0; nf < 8; nf++) \
            *(float2*)&orow_[nf * 8 + kq * 2] = \
                make_float2(XF(acc[mf][nf][2 * h]), XF(acc[mf][nf][2 * h + 1])); }

#define XF_TF(x)  tf32r(x)
#define XF_OUT(x) ((x) + 0.001f)

// ---------------- prep kernels ----------------
__global__ void round_pv(const float* __restrict__ pv) {
    int i = blockIdx.x * 1024 + threadIdx.x;
    g_pv[i] = tf32r(pv[i]);
}

__global__ void transpose3(const float* __restrict__ Wk,
                           const float* __restrict__ Wq,
                           const float* __restrict__ Wv) {
    __shared__ float tile[32][33];
    const float* src;
    float* dst;
    if (blockIdx.z == 0)      { src = Wk; dst = g_WkT; }
    else if (blockIdx.z == 1) { src = Wq; dst = g_WqT; }
    else                      { src = Wv; dst = g_WvT; }
    int x = blockIdx.x * 32 + threadIdx.x;
    int y = blockIdx.y * 32 + threadIdx.y;
#pragma unroll
    for (int i = 0; i < 32; i += 8)
        tile[threadIdx.y + i][threadIdx.x] = src[(size_t)(y + i) * Vv + x];
    __syncthreads();
    x = blockIdx.y * 32 + threadIdx.x;
    y = blockIdx.x * 32 + threadIdx.y;
#pragma unroll
    for (int i = 0; i < 32; i += 8)
        dst[(size_t)(y + i) * Vv + x] = tf32r(tile[threadIdx.x][threadIdx.y + i]);
}

// Gv[b][o][s] = WvT[idx[b][s]][o]   (z even)
// Cg[b][a][s'] = CT[idx[b][s']][a]  (z odd)
__global__ void gather2(const int* __restrict__ idx) {
    __shared__ float tile[32][33];
    const int z = blockIdx.z;
    const int b = z >> 1;
    const float* WT = (z & 1) ? g_CT : g_WvT;
    float* G        = (z & 1) ? g_Cg : g_Gv;
    const int o0 = blockIdx.x * 32, s0 = blockIdx.y * 32;
    const int tx = threadIdx.x, ty = threadIdx.y;
#pragma unroll
    for (int i = 0; i < 32; i += 8) {
        const int row = idx[b * Tt + s0 + ty + i];
        tile[ty + i][tx] = WT[(size_t)row * Vv + o0 + tx];
    }
    __syncthreads();
#pragma unroll
    for (int i = 0; i < 32; i += 8)
        G[((size_t)(b * Vv + o0 + ty + i)) * Tt + s0 + tx] = tile[tx][ty + i];
}

// ---------------------------------------------------------------------------
// Kernel A: CT[i][a] = sum_o WkT[i][o] * WqT[a][o]
// ---------------------------------------------------------------------------
__global__ __launch_bounds__(NTH)
void kernel_CT() {
    const int i0 = blockIdx.y * BM;
    const int a0 = blockIdx.x * BN;
    GEMM_PROLOG();
    const float* as = g_WkT + (size_t)(i0 + tid) * Vv;
    const float* bs = g_WqT + (size_t)(a0 + tid) * Vv;
    auto fill = [&](int kt, uint32_t bo) {
        const int o0 = kt * BK;
#pragma unroll
        for (int ch = 0; ch < 8; ch++) {
            const uint32_t off = bo + (((uint32_t)(ch * 16)) ^ fxg);
            cpa16(fA + off, as + o0 + ch * 4);
            cpa16(fB + off, bs + o0 + ch * 4);
        }
    };
    const int nt = Vv / BK;
    GEMM_LOOP(nt, fill);
    GEMM_EPI(g_CT, Vv, i0, a0, XF_TF);
}

// ---------------------------------------------------------------------------
// Kernel B: Ah[b][a][s] = sum_{s'<=s} Cg[b][a][s'] * pv[s-s']   (causal Toeplitz)
// A = Cg (cp.async), B[s][s'] = pv[s-s'] generated + masked.
// ---------------------------------------------------------------------------
__global__ __launch_bounds__(NTH)
void kernel_Ah() {
    const int b  = blockIdx.z;
    const int a0 = blockIdx.y * BM;
    const int s0 = blockIdx.x * BN;
    GEMM_PROLOG();
    const float* as = g_Cg + ((size_t)(b * Vv + a0 + tid)) * Tt;
    const int s = s0 + tid;
    auto fill = [&](int kt, uint32_t bo) {
        const int sp0 = kt * BK;
#pragma unroll
        for (int ch = 0; ch < 8; ch++) {
            const uint32_t off = bo + (((uint32_t)(ch * 16)) ^ fxg);
            cpa16(fA + off, as + sp0 + ch * 4);
            const int d = s - (sp0 + ch * 4);
            float4 v;
            v.x = (d     >= 0) ? g_pv[d]     : 0.f;
            v.y = (d - 1 >= 0) ? g_pv[d - 1] : 0.f;
            v.z = (d - 2 >= 0) ? g_pv[d - 2] : 0.f;
            v.w = (d - 3 >= 0) ? g_pv[d - 3] : 0.f;
            *(float4*)(fBp + off) = v;
        }
    };
    const int nt = s0 / BK + BN / BK;
    GEMM_LOOP(nt, fill);
    GEMM_EPI(g_Ah + (size_t)b * Vv * Tt, Tt, a0, s0, XF_TF);
}

// ---------------------------------------------------------------------------
// Kernel C: out[b][t][o] = 1e-3 + sum_{s<=t} Ah[b][idx[b][t]][s] * Gv[b][o][s]
// ---------------------------------------------------------------------------
__global__ __launch_bounds__(NTH)
void kernel_out(const int* __restrict__ idx, float* __restrict__ out) {
    const int b  = blockIdx.z;
    const int t0 = blockIdx.y * BM;
    const int n0 = blockIdx.x * BN;
    GEMM_PROLOG();
    const int t = t0 + tid;
    const int ia = idx[b * Tt + t];
    const float* as = g_Ah + ((size_t)(b * Vv + ia)) * Tt;
    const float* bs = g_Gv + ((size_t)(b * Vv + n0 + tid)) * Tt;
    const int nt = t0 / BK + BN / BK;
    auto fill = [&](int kt, uint32_t bo) {
        const int sp0 = kt * BK;
        if (kt >= nt - 4) {
#pragma unroll
            for (int ch = 0; ch < 8; ch++) {
                const uint32_t off = bo + (((uint32_t)(ch * 16)) ^ fxg);
                const int sb = sp0 + ch * 4;
                float4 v = *(const float4*)(as + sb);
                v.x = (sb     <= t) ? v.x : 0.f;
                v.y = (sb + 1 <= t) ? v.y : 0.f;
                v.z = (sb + 2 <= t) ? v.z : 0.f;
                v.w = (sb + 3 <= t) ? v.w : 0.f;
                *(float4*)(fAp + off) = v;
                cpa16(fB + off, bs + sb);
            }
        } else {
#pragma unroll
            for (int ch = 0; ch < 8; ch++) {
                const uint32_t off = bo + (((uint32_t)(ch * 16)) ^ fxg);
                cpa16(fA + off, as + sp0 + ch * 4);
                cpa16(fB + off, bs + sp0 + ch * 4);
            }
        }
    };
    GEMM_LOOP(nt, fill);
    GEMM_EPI(out + (size_t)b * Tt * Vv, Vv, t0, n0, XF_OUT);
}

// ---------------------------------------------------------------------------
extern "C" void kernel_launch(void* const* d_in, const int* in_sizes, int n_in,
                              void* d_out, int out_size) {
    const int*   idx = (const int*)d_in[0];
    const float* pv  = (const float*)d_in[1];
    const float* Wk  = (const float*)d_in[2];
    const float* Wq  = (const float*)d_in[3];
    const float* Wv  = (const float*)d_in[4];
    float* out = (float*)d_out;

    const int dynsmem = 3 * BUFB;  // 96 KB
    cudaFuncSetAttribute(kernel_CT,  cudaFuncAttributeMaxDynamicSharedMemorySize, dynsmem);
    cudaFuncSetAttribute(kernel_Ah,  cudaFuncAttributeMaxDynamicSharedMemorySize, dynsmem);
    cudaFuncSetAttribute(kernel_out, cudaFuncAttributeMaxDynamicSharedMemorySize, dynsmem);

    round_pv  <<<Tt / 1024, 1024>>>(pv);
    transpose3<<<dim3(Vv / 32, Vv / 32, 3), dim3(32, 8)>>>(Wk, Wq, Wv);
    kernel_CT <<<dim3(Vv / BN, Vv / BM, 1), NTH, dynsmem>>>();
    gather2   <<<dim3(Vv / 32, Tt / 32, Bb * 2), dim3(32, 8)>>>(idx);
    kernel_Ah <<<dim3(Tt / BN, Vv / BM, Bb), NTH, dynsmem>>>();
    kernel_out<<<dim3(Vv / BN, Tt / BM, Bb), NTH, dynsmem>>>(idx, out);
}